// round 3
// baseline (speedup 1.0000x reference)
#include <cuda_runtime.h>
#include <cuda_bf16.h>
#include <math.h>

// Problem constants
#define BB   32
#define INF  128
#define HH   1024
#define OUTF 128
#define KCAT (INF + HH)   // 1152
#define TPB  256
#define RPT  8            // rows per tile (= warps per block)

#define NT_H   ((BB * HH) / RPT)    // 4096 tiles for an H-output layer
#define NT_O   ((BB * OUTF) / RPT)  // 512 tiles for the Wo head
#define NT_HEADS (NT_H + NT_O)      // 4608

// Scratch (allocation-free rule: __device__ globals)
__device__ float g_c0[BB * HH];
__device__ float g_c1[BB * HH];
__device__ float g_c2[BB * HH];
__device__ float g_logits[BB * OUTF];
__device__ unsigned g_bar_count = 0;
__device__ unsigned g_bar_gen   = 0;

// ---------------- grid-wide barrier (all blocks resident by construction) ----
__device__ __forceinline__ void grid_barrier(int nb) {
    __syncthreads();
    if (threadIdx.x == 0) {
        unsigned my = *(volatile unsigned*)&g_bar_gen;   // read gen BEFORE arriving
        __threadfence();                                 // publish our stores
        unsigned ticket = atomicAdd(&g_bar_count, 1u);
        if (ticket == (unsigned)nb - 1u) {
            g_bar_count = 0;
            __threadfence();
            atomicAdd(&g_bar_gen, 1u);                   // release
        } else {
            while (*(volatile unsigned*)&g_bar_gen == my) __nanosleep(64);
        }
        __threadfence();                                 // acquire
    }
    __syncthreads();
}

// L2 prefetch of [p, p+bytes) in 128B lines, block-cooperative (correctness-neutral)
__device__ __forceinline__ void prefetch_l2(const char* p, int bytes) {
    for (int i = threadIdx.x * 128; i < bytes; i += TPB * 128)
        asm volatile("prefetch.global.L2 [%0];" :: "l"(p + i));
}

// Process tiles [t_begin, t_end) of one layer. Tile t = rows [t*8, t*8+8) (one per warp).
// Activation vector staged in smem once per batch change.
template <int K, bool TANH, bool CONCAT>
__device__ __forceinline__ void run_tiles(
    const float* __restrict__ W, const float* __restrict__ bias,
    const float* __restrict__ actA, const float* __restrict__ actB,
    float* __restrict__ outp, int Hout,
    int t_begin, int t_end, float* xs, int& staged_b)
{
    const int warp = threadIdx.x >> 5;
    const int lane = threadIdx.x & 31;
    float4* xv = reinterpret_cast<float4*>(xs);

    for (int t = t_begin; t < t_end; ++t) {
        const int rowbase = t * RPT;
        const int b = rowbase / Hout;

        if (b != staged_b) {
            __syncthreads();
            if (CONCAT) {
                const float4* xa = reinterpret_cast<const float4*>(actA + (size_t)b * INF);
                const float4* xb = reinterpret_cast<const float4*>(actB + (size_t)b * HH);
                for (int i = threadIdx.x; i < K / 4; i += TPB)
                    xv[i] = (i < INF / 4) ? xa[i] : xb[i - INF / 4];
            } else {
                const float4* src = reinterpret_cast<const float4*>(actA + (size_t)b * K);
                for (int i = threadIdx.x; i < K / 4; i += TPB)
                    xv[i] = src[i];
            }
            __syncthreads();
            staged_b = b;
        }

        const int row = rowbase + warp;
        const int o   = row - b * Hout;
        const float4* __restrict__ Wr = reinterpret_cast<const float4*>(W + (size_t)row * K);
        constexpr int NIT = K / 128;

        float4 w[NIT];
#pragma unroll
        for (int j = 0; j < NIT; j++)
            w[j] = __ldcs(Wr + j * 32 + lane);

        float sum = 0.f;
#pragma unroll
        for (int j = 0; j < NIT; j++) {
            float4 v = xv[j * 32 + lane];
            sum += w[j].x * v.x + w[j].y * v.y + w[j].z * v.z + w[j].w * v.w;
        }
#pragma unroll
        for (int off = 16; off; off >>= 1)
            sum += __shfl_xor_sync(0xFFFFFFFFu, sum, off);

        if (lane == 0)
            outp[row] = TANH ? tanhf(sum + bias[o]) : (sum + bias[o]);
    }
}

__device__ __forceinline__ void chunk_range(int ntiles, int nb, int bid, int& s, int& e) {
    int per = (ntiles + nb - 1) / nb;
    s = bid * per; if (s > ntiles) s = ntiles;
    e = s + per;   if (e > ntiles) e = ntiles;
}

__global__ __launch_bounds__(TPB, 4) void fused_rnn_kernel(
    const float* __restrict__ x,  const float* __restrict__ hidden,
    const float* __restrict__ W0, const float* __restrict__ b0,
    const float* __restrict__ W1, const float* __restrict__ b1,
    const float* __restrict__ W2, const float* __restrict__ b2,
    const float* __restrict__ Wh, const float* __restrict__ bh,
    const float* __restrict__ Wo, const float* __restrict__ bo,
    float* __restrict__ out, float* __restrict__ new_hidden, int nb)
{
    __shared__ float xs[KCAT];
    const int bid = blockIdx.x;
    int staged;

    int sH, eH;                  // per-block tile range for H-output layers (shared shape)
    chunk_range(NT_H, nb, bid, sH, eH);

    // ---- Layer 0: W0 * cat(x, hidden), tanh -> c0 ----
    staged = -1;
    run_tiles<KCAT, true, true>(W0, b0, x, hidden, g_c0, HH, sH, eH, xs, staged);
    // Fill barrier bubble: pull the first 2 tiles of our W1 chunk into L2.
    if (sH < eH) {
        int ntile = min(2, eH - sH);
        prefetch_l2((const char*)(W1 + (size_t)sH * RPT * HH), ntile * RPT * HH * 4);
    }
    grid_barrier(nb);

    // ---- Layer 1 ----
    staged = -1;
    run_tiles<HH, true, false>(W1, b1, g_c0, nullptr, g_c1, HH, sH, eH, xs, staged);
    if (sH < eH) {
        int ntile = min(2, eH - sH);
        prefetch_l2((const char*)(W2 + (size_t)sH * RPT * HH), ntile * RPT * HH * 4);
    }
    grid_barrier(nb);

    // ---- Layer 2 ----
    staged = -1;
    run_tiles<HH, true, false>(W2, b2, g_c1, nullptr, g_c2, HH, sH, eH, xs, staged);
    {
        int s, e; chunk_range(NT_HEADS, nb, bid, s, e);
        if (s < e && s < NT_H) {
            int ntile = min(2, min(e, NT_H) - s);
            prefetch_l2((const char*)(Wh + (size_t)s * RPT * HH), ntile * RPT * HH * 4);
        }
    }
    grid_barrier(nb);

    // ---- Heads: Wh (tanh -> new_hidden) then Wo (logits), one combined partition ----
    {
        int s, e; chunk_range(NT_HEADS, nb, bid, s, e);
        staged = -1;
        int sWh = min(s, NT_H), eWh = min(e, NT_H);
        run_tiles<HH, true, false>(Wh, bh, g_c2, nullptr, new_hidden, HH, sWh, eWh, xs, staged);
        int sWo = max(s, NT_H) - NT_H, eWo = max(e, NT_H) - NT_H;
        // same act (g_c2) and same batch numbering -> keep staged across the two calls
        run_tiles<HH, false, false>(Wo, bo, g_c2, nullptr, g_logits, OUTF, sWo, eWo, xs, staged);
    }
    grid_barrier(nb);

    // ---- log_softmax: blocks 0..31, warp 0 handles batch=bid (4 vals/lane) ----
    if (bid < BB && threadIdx.x < 32) {
        const int lane = threadIdx.x;
        const float* l = g_logits + bid * OUTF;
        float v[4];
#pragma unroll
        for (int i = 0; i < 4; i++) v[i] = l[i * 32 + lane];
        float m = fmaxf(fmaxf(v[0], v[1]), fmaxf(v[2], v[3]));
#pragma unroll
        for (int off = 16; off; off >>= 1)
            m = fmaxf(m, __shfl_xor_sync(0xFFFFFFFFu, m, off));
        float ssum = 0.f;
#pragma unroll
        for (int i = 0; i < 4; i++) ssum += __expf(v[i] - m);
#pragma unroll
        for (int off = 16; off; off >>= 1)
            ssum += __shfl_xor_sync(0xFFFFFFFFu, ssum, off);
        float lse = m + logf(ssum);
#pragma unroll
        for (int i = 0; i < 4; i++)
            out[bid * OUTF + i * 32 + lane] = v[i] - lse;
    }
}

extern "C" void kernel_launch(void* const* d_in, const int* in_sizes, int n_in,
                              void* d_out, int out_size) {
    const float* x      = (const float*)d_in[0];
    const float* hidden = (const float*)d_in[1];
    const float* W0 = (const float*)d_in[2];
    const float* b0 = (const float*)d_in[3];
    const float* W1 = (const float*)d_in[4];
    const float* b1 = (const float*)d_in[5];
    const float* W2 = (const float*)d_in[6];
    const float* b2 = (const float*)d_in[7];
    const float* Wh = (const float*)d_in[8];
    const float* bh = (const float*)d_in[9];
    const float* Wo = (const float*)d_in[10];
    const float* bo = (const float*)d_in[11];

    float* out = (float*)d_out;                 // [B*OUT] log_softmax, then [B*H] new_hidden
    float* new_hidden = out + BB * OUTF;

    // Grid = guaranteed co-resident block count (barrier deadlock-freedom).
    int dev = 0, sms = 0, occ = 0;
    cudaGetDevice(&dev);
    cudaDeviceGetAttribute(&sms, cudaDevAttrMultiProcessorCount, dev);
    cudaOccupancyMaxActiveBlocksPerMultiprocessor(&occ, fused_rnn_kernel, TPB, 0);
    if (occ < 1) occ = 1;
    int nb = sms * occ;
    if (nb > NT_H) nb = NT_H;   // keep >=1 tile per chunk arithmetic sane
    if (nb < BB) nb = BB;       // softmax needs 32 blocks

    fused_rnn_kernel<<<nb, TPB>>>(x, hidden, W0, b0, W1, b1, W2, b2,
                                  Wh, bh, Wo, bo, out, new_hidden, nb);

    (void)in_sizes; (void)n_in; (void)out_size;
}